// round 11
// baseline (speedup 1.0000x reference)
#include <cuda_runtime.h>
#include <cuda_bf16.h>
#include <stdint.h>

#define OUT_CH 32
#define MIN_BLOCKS 64

__device__ float g_Wt[100000 * OUT_CH];       // transposed W, L2-resident 12.8 MB
__device__ int   g_part[MIN_BLOCKS];          // row-min partials (rewritten every call)
__device__ int   g_rowmin;                    // finalized by last-arriving prep block
__device__ unsigned g_ticket;                 // persistent; mod-64 logic is replay-safe

// ---------------------------------------------------------------------------
// K1 (fused prep): blocks [0, NB): transpose W[32,N]->Wt[N,32] (float4 reads,
//                  4 nodes per thread) and out[n,:]=b.
//                  blocks [NB, NB+64): row-min partials; last-arriving block
//                  finalizes g_rowmin (ticket counter; no reset kernel needed).
// ---------------------------------------------------------------------------
__global__ void prep_kernel(const float* __restrict__ W, const float* __restrict__ b,
                            const int* __restrict__ rows, float* __restrict__ out,
                            int N, int E, int NB) {
    if ((int)blockIdx.x < NB) {
        // each thread handles 4 consecutive nodes -> float4 loads of W rows
        int n0 = (blockIdx.x * blockDim.x + threadIdx.x) * 4;
        if (n0 >= N) return;
        int nmax = min(4, N - n0);
        if (nmax == 4 && (N & 3) == 0) {
            float4 v[OUT_CH];            // v[c] = W[c, n0..n0+3]
            #pragma unroll
            for (int c = 0; c < OUT_CH; c++)
                v[c] = __ldg(reinterpret_cast<const float4*>(&W[(size_t)c * N + n0]));
            #pragma unroll
            for (int k = 0; k < 4; k++) {
                float* wt = &g_Wt[(size_t)(n0 + k) * OUT_CH];
                float4* dst = reinterpret_cast<float4*>(wt);
                const float* vk = &((&v[0].x)[k]);   // not used; explicit below
                #pragma unroll
                for (int j = 0; j < OUT_CH / 4; j++) {
                    float e0 = (&v[4*j+0].x)[k];
                    float e1 = (&v[4*j+1].x)[k];
                    float e2 = (&v[4*j+2].x)[k];
                    float e3 = (&v[4*j+3].x)[k];
                    dst[j] = make_float4(e0, e1, e2, e3);
                }
                (void)vk;
            }
        } else {
            for (int k = 0; k < nmax; k++) {
                int n = n0 + k;
                float vv[OUT_CH];
                #pragma unroll
                for (int c = 0; c < OUT_CH; c++)
                    vv[c] = __ldg(&W[(size_t)c * N + n]);
                float4* dst = reinterpret_cast<float4*>(&g_Wt[(size_t)n * OUT_CH]);
                #pragma unroll
                for (int j = 0; j < OUT_CH / 4; j++)
                    dst[j] = make_float4(vv[4*j+0], vv[4*j+1], vv[4*j+2], vv[4*j+3]);
            }
        }
        // out[n0..n0+nmax, :] = b
        float4 b0 = __ldg(reinterpret_cast<const float4*>(b) + 0);
        float4 b1 = __ldg(reinterpret_cast<const float4*>(b) + 1);
        float4 b2 = __ldg(reinterpret_cast<const float4*>(b) + 2);
        float4 b3 = __ldg(reinterpret_cast<const float4*>(b) + 3);
        float4 b4 = __ldg(reinterpret_cast<const float4*>(b) + 4);
        float4 b5 = __ldg(reinterpret_cast<const float4*>(b) + 5);
        float4 b6 = __ldg(reinterpret_cast<const float4*>(b) + 6);
        float4 b7 = __ldg(reinterpret_cast<const float4*>(b) + 7);
        for (int k = 0; k < nmax; k++) {
            float4* o = reinterpret_cast<float4*>(&out[(size_t)(n0 + k) * OUT_CH]);
            o[0]=b0; o[1]=b1; o[2]=b2; o[3]=b3; o[4]=b4; o[5]=b5; o[6]=b6; o[7]=b7;
        }
    } else {
        __shared__ int s_wmin[8];
        __shared__ int s_last;
        int blk = blockIdx.x - NB;                    // 0..63
        int i = blk * blockDim.x + threadIdx.x;
        int stride = MIN_BLOCKS * blockDim.x;
        int m = 0x7fffffff;
        for (; i < E; i += stride)
            m = min(m, __ldg(&rows[i]));
        #pragma unroll
        for (int off = 16; off > 0; off >>= 1)
            m = min(m, __shfl_xor_sync(0xffffffffu, m, off));
        if ((threadIdx.x & 31) == 0) s_wmin[threadIdx.x >> 5] = m;
        __syncthreads();
        if (threadIdx.x == 0) {
            int bm = s_wmin[0];
            #pragma unroll
            for (int k = 1; k < 8; k++) bm = min(bm, s_wmin[k]);
            g_part[blk] = bm;                         // plain store
            __threadfence();
            unsigned t = atomicAdd(&g_ticket, 1u);    // persistent; mod-64 replay-safe
            s_last = ((t & 63u) == 63u) ? 1 : 0;
        }
        __syncthreads();
        if (s_last && threadIdx.x < 32) {
            volatile int* vp = g_part;
            int a = min(vp[threadIdx.x], vp[threadIdx.x + 32]);
            #pragma unroll
            for (int off = 16; off > 0; off >>= 1)
                a = min(a, __shfl_xor_sync(0xffffffffu, a, off));
            if (threadIdx.x == 0) g_rowmin = a;
        }
    }
}

// ---------------------------------------------------------------------------
// K2: scatter — R4-proven config: 256 threads, 8 threads per edge-pair slot,
// each thread handles channel-quad t of TWO independent edges, single uniform
// g_rowmin load (no per-block preamble).
// ---------------------------------------------------------------------------
__global__ void __launch_bounds__(256) scatter_kernel(const int* __restrict__ ei,
                                                      int E, int N,
                                                      float* __restrict__ out) {
    int minr = g_rowmin;                              // single uniform load

    int half = (E + 1) >> 1;
    long long gtid = (long long)blockIdx.x * blockDim.x + threadIdx.x;
    long long g = gtid >> 3;
    int t = (int)(gtid & 7);
    if (g >= half) return;

    int e0 = (int)g;
    int e1 = e0 + half;
    bool has1 = (e1 < E);

    // front-load all index reads (independent)
    int row0 = __ldg(&ei[e0]);
    int col0 = __ldg(&ei[E + e0]);
    int row1 = has1 ? __ldg(&ei[e1]) : 0;
    int col1 = has1 ? __ldg(&ei[E + e1]) : 0;

    row0 -= minr;  row1 -= minr;
    bool ok0 = (unsigned)row0 < (unsigned)N && (unsigned)col0 < (unsigned)N;
    bool ok1 = has1 && (unsigned)row1 < (unsigned)N && (unsigned)col1 < (unsigned)N;

    // independent gathers (both in flight)
    float4 v0, v1;
    if (ok0) v0 = __ldg(reinterpret_cast<const float4*>(&g_Wt[(size_t)col0 * OUT_CH]) + t);
    if (ok1) v1 = __ldg(reinterpret_cast<const float4*>(&g_Wt[(size_t)col1 * OUT_CH]) + t);

    if (ok0) {
        float* dst = &out[(size_t)row0 * OUT_CH + t * 4];
        asm volatile("red.global.add.v4.f32 [%0], {%1, %2, %3, %4};"
                     :: "l"(dst), "f"(v0.x), "f"(v0.y), "f"(v0.z), "f"(v0.w) : "memory");
    }
    if (ok1) {
        float* dst = &out[(size_t)row1 * OUT_CH + t * 4];
        asm volatile("red.global.add.v4.f32 [%0], {%1, %2, %3, %4};"
                     :: "l"(dst), "f"(v1.x), "f"(v1.y), "f"(v1.z), "f"(v1.w) : "memory");
    }
}

// ---------------------------------------------------------------------------
extern "C" void kernel_launch(void* const* d_in, const int* in_sizes, int n_in,
                              void* d_out, int out_size) {
    const int*   ei = (const int*)d_in[0];     // [2, E]
    const float* W  = (const float*)d_in[1];   // [32, N]
    const float* b  = (const float*)d_in[2];   // [32]
    float* out = (float*)d_out;                // [N, 32]

    int E = in_sizes[0] / 2;
    int N = in_sizes[1] / OUT_CH;

    int pthreads = 256;
    int NB = ((N + 3) / 4 + pthreads - 1) / pthreads;   // 4 nodes per thread
    prep_kernel<<<NB + MIN_BLOCKS, pthreads>>>(W, b, ei, out, N, E, NB);

    int sthreads = 256;
    long long half = (E + 1) >> 1;
    long long work = half * 8;
    int blocks = (int)((work + sthreads - 1) / sthreads);
    scatter_kernel<<<blocks, sthreads>>>(ei, E, N, out);
}